// round 7
// baseline (speedup 1.0000x reference)
#include <cuda_runtime.h>
#include <math.h>
#include <math_constants.h>

#define N_TOK 4096
#define DMODEL 256
#define NHEAD 4
#define DHEAD 64
#define TOPK 30
#define SCALE 0.25f
#define LN_EPS 1e-5f

typedef unsigned long long ull;

// ---------------- scratch (static device allocations; no runtime alloc) ----------
__device__ float g_q[N_TOK * DMODEL];
__device__ float g_k[N_TOK * DMODEL];
__device__ float g_v[N_TOK * DMODEL];
__device__ float g_ctx[N_TOK * DMODEL];
__device__ float g_resid[N_TOK * DMODEL];
__device__ float g_scores[(size_t)NHEAD * N_TOK * N_TOK];  // 256 MB score scratch

// ---------------- packed fp32x2 helpers ------------------------------------------
__device__ __forceinline__ void fma2(ull& d, ull a, ull b) {
    asm("fma.rn.f32x2 %0, %1, %2, %0;" : "+l"(d) : "l"(a), "l"(b));
}
__device__ __forceinline__ float2 unpack2(ull v) {
    float2 f;
    asm("mov.b64 {%0, %1}, %2;" : "=f"(f.x), "=f"(f.y) : "l"(v));
    return f;
}
// monotone float->uint map (ascending)
__device__ __forceinline__ unsigned ford(float f) {
    unsigned u = __float_as_uint(f);
    return (u & 0x80000000u) ? ~u : (u | 0x80000000u);
}
__device__ __forceinline__ float unford(unsigned u) {
    return __uint_as_float((u & 0x80000000u) ? (u & 0x7FFFFFFFu) : ~u);
}

// ---- warp bitonic: sort 32 ull (1/lane) DESCENDING across lanes -------------------
__device__ __forceinline__ ull bsort32_desc(ull k, int lane) {
#pragma unroll
    for (int size = 2; size <= 32; size <<= 1) {
#pragma unroll
        for (int stride = size >> 1; stride >= 1; stride >>= 1) {
            ull o = __shfl_xor_sync(0xFFFFFFFFu, k, stride);
            bool desc = ((lane & size) == 0);
            bool lower = ((lane & stride) == 0);
            bool takemax = (lower == desc);
            ull mx = (k > o) ? k : o;
            ull mn = (k > o) ? o : k;
            k = takemax ? mx : mn;
        }
    }
    return k;
}
// bitonic merge (input bitonic) -> descending
__device__ __forceinline__ ull bmerge32_desc(ull k, int lane) {
#pragma unroll
    for (int stride = 16; stride >= 1; stride >>= 1) {
        ull o = __shfl_xor_sync(0xFFFFFFFFu, k, stride);
        bool lower = ((lane & stride) == 0);
        ull mx = (k > o) ? k : o;
        ull mn = (k > o) ? o : k;
        k = lower ? mx : mn;
    }
    return k;
}

// ---------------- 32x64-tile fp32 GEMM body: C = A @ B^T (+bias)(+res) -----------
// 256 threads, micro 2x4; grid.x = cols/64, grid.y = rows/32. Higher block-count
// variant for the parallelism-starved projection GEMMs.
template <bool ADD_RES>
__device__ __forceinline__ void gemm32_body(const float* __restrict__ A,
                                            const float* __restrict__ B,
                                            const float* __restrict__ bias,
                                            const float* __restrict__ res,
                                            float* __restrict__ C) {
    __shared__ ull As[32 * 33];
    __shared__ ull Bs[64 * 33];
    const int tid = threadIdx.x;
    const int bm = blockIdx.y * 32;
    const int bn = blockIdx.x * 64;
    const int qg = tid >> 4;  // 0..15, 2 rows each
    const int kg = tid & 15;  // 0..15, 4 cols each

    ull acc[2][4];
#pragma unroll
    for (int a = 0; a < 2; ++a)
#pragma unroll
        for (int b = 0; b < 4; ++b) acc[a][b] = 0ull;

    for (int kk = 0; kk < 256; kk += 64) {
        __syncthreads();
#pragma unroll
        for (int i = 0; i < 4; ++i) {
            int idx = tid + i * 256;
            int r = idx >> 5, c = idx & 31;
            As[r * 33 + c] = *(const ull*)(A + (size_t)(bm + r) * 256 + kk + c * 2);
        }
#pragma unroll
        for (int i = 0; i < 8; ++i) {
            int idx = tid + i * 256;
            int r = idx >> 5, c = idx & 31;
            Bs[r * 33 + c] = *(const ull*)(B + (size_t)(bn + r) * 256 + kk + c * 2);
        }
        __syncthreads();
#pragma unroll 8
        for (int d2 = 0; d2 < 32; ++d2) {
            ull qv[2], kv[4];
#pragma unroll
            for (int a = 0; a < 2; ++a) qv[a] = As[(qg * 2 + a) * 33 + d2];
#pragma unroll
            for (int b = 0; b < 4; ++b) kv[b] = Bs[(kg * 4 + b) * 33 + d2];
#pragma unroll
            for (int a = 0; a < 2; ++a)
#pragma unroll
                for (int b = 0; b < 4; ++b) fma2(acc[a][b], qv[a], kv[b]);
        }
    }
#pragma unroll
    for (int a = 0; a < 2; ++a) {
        int row = bm + qg * 2 + a;
#pragma unroll
        for (int b = 0; b < 4; ++b) {
            int col = bn + kg * 4 + b;
            float2 f = unpack2(acc[a][b]);
            float v = f.x + f.y + bias[col];
            if (ADD_RES) v += res[(size_t)row * 256 + col];
            C[(size_t)row * 256 + col] = v;
        }
    }
}

// ---------------- K1: fused Q/K/V projections -------------------------------------
__global__ __launch_bounds__(256) void proj_kernel(
    const float* __restrict__ q_in, const float* __restrict__ k_in,
    const float* __restrict__ v_in, const float* __restrict__ Wq,
    const float* __restrict__ bq, const float* __restrict__ Wk,
    const float* __restrict__ bk, const float* __restrict__ Wv,
    const float* __restrict__ bv) {
    const float *A, *B, *bias;
    float* C;
    if (blockIdx.z == 0) { A = q_in; B = Wq; bias = bq; C = g_q; }
    else if (blockIdx.z == 1) { A = k_in; B = Wk; bias = bk; C = g_k; }
    else { A = v_in; B = Wv; bias = bv; C = g_v; }
    gemm32_body<false>(A, B, bias, nullptr, C);
}

// ---------------- K2a: dense score GEMM -> g_scores; zero attn tile ----------------
// grid: (64 kb, 32 qb, 4 h). block 256. tile 128(q) x 64(k). micro 8x4 in ull.
__global__ __launch_bounds__(256, 2) void score_kernel(float* __restrict__ attn) {
    __shared__ ull Qs[128 * 32];
    __shared__ ull Ks[64 * 32];
    const int tid = threadIdx.x;
    const int h = blockIdx.z;
    const int qb0 = blockIdx.y * 128;
    const int kb0 = blockIdx.x * 64;
    const int kg = tid & 15;   // 16 col-groups of 4
    const int qg = tid >> 4;   // 16 row-groups of 8

    // zero-fill this block's attn tile (rows qb0..+128, cols kb0..+64), streaming
    {
        const float4 z4 = make_float4(0.f, 0.f, 0.f, 0.f);
#pragma unroll
        for (int i = 0; i < 8; ++i) {
            int idx = tid + i * 256;
            int r = idx >> 4, c4 = idx & 15;
            __stcs((float4*)(attn + (size_t)(h * N_TOK + qb0 + r) * N_TOK + kb0 +
                             c4 * 4),
                   z4);
        }
    }

    // fill Q tile: 4096 ull, swizzle c ^ (r>>3)
#pragma unroll
    for (int i = 0; i < 16; ++i) {
        int idx = tid + i * 256;
        int r = idx >> 5, c = idx & 31;
        Qs[(r << 5) | (c ^ (r >> 3))] =
            *(const ull*)(g_q + (size_t)(qb0 + r) * 256 + h * 64 + c * 2);
    }
    // fill K tile: 2048 ull, swizzle c ^ (r>>2)
#pragma unroll
    for (int i = 0; i < 8; ++i) {
        int idx = tid + i * 256;
        int r = idx >> 5, c = idx & 31;
        Ks[(r << 5) | (c ^ (r >> 2))] =
            *(const ull*)(g_k + (size_t)(kb0 + r) * 256 + h * 64 + c * 2);
    }
    __syncthreads();

    ull acc[8][4];
#pragma unroll
    for (int a = 0; a < 8; ++a)
#pragma unroll
        for (int b = 0; b < 4; ++b) acc[a][b] = 0ull;

#pragma unroll 4
    for (int d2 = 0; d2 < 32; ++d2) {
        ull qv[8], kv[4];
#pragma unroll
        for (int a = 0; a < 8; ++a) qv[a] = Qs[((qg * 8 + a) << 5) | (d2 ^ qg)];
#pragma unroll
        for (int b = 0; b < 4; ++b) kv[b] = Ks[((kg * 4 + b) << 5) | (d2 ^ kg)];
#pragma unroll
        for (int a = 0; a < 8; ++a)
#pragma unroll
            for (int b = 0; b < 4; ++b) fma2(acc[a][b], qv[a], kv[b]);
    }

#pragma unroll
    for (int a = 0; a < 8; ++a) {
        int row = qb0 + qg * 8 + a;
        float4 o;
        float2 f0 = unpack2(acc[a][0]);
        float2 f1 = unpack2(acc[a][1]);
        float2 f2 = unpack2(acc[a][2]);
        float2 f3 = unpack2(acc[a][3]);
        o.x = (f0.x + f0.y) * SCALE;
        o.y = (f1.x + f1.y) * SCALE;
        o.z = (f2.x + f2.y) * SCALE;
        o.w = (f3.x + f3.y) * SCALE;
        __stcs((float4*)(g_scores + ((size_t)(h * N_TOK + row)) * N_TOK + kb0 +
                         kg * 4),
               o);
    }
}

// ---------------- K2b: warp-per-row top-30, group-ballot fast path ----------------
__global__ __launch_bounds__(256) void topk_kernel(float* __restrict__ attn) {
    __shared__ ull bufs[8][64];
    const unsigned FULL = 0xFFFFFFFFu;
    const int warp = threadIdx.x >> 5, lane = threadIdx.x & 31;
    const int row = blockIdx.x * 8 + warp;  // = h*4096 + n
    const int h = row >> 12;
    const int n = row & 4095;
    const float4* p4 = (const float4*)(g_scores + (size_t)row * N_TOK);
    ull* buf = bufs[warp];

    ull L = 0ull;                    // sorted desc top-32 (1/lane)
    ull tau = 0ull;                  // 30th-best 64-bit key so far
    float tau_s = -CUDART_INF_F;     // fp32 score of tau (fast-path filter)
    int cnt = 0;                     // pending candidates in buf

    float4 v = __ldcs(p4 + lane);
    for (int c = 0; c < 32; ++c) {
        float4 nv = v;
        if (c + 1 < 32) nv = __ldcs(p4 + (c + 1) * 32 + lane);  // prefetch
        float m4 = fmaxf(fmaxf(v.x, v.y), fmaxf(v.z, v.w));
        // fast path: one ballot per 4 elements. s > tau_s => key > tau (ford
        // monotone); equals fall into the exact 64-bit slow path.
        if (__ballot_sync(FULL, m4 >= tau_s) != 0) {
#pragma unroll
            for (int j = 0; j < 4; ++j) {
                float s = (j == 0) ? v.x : (j == 1) ? v.y : (j == 2) ? v.z : v.w;
                int col = c * 128 + lane * 4 + j;
                ull key = ((ull)ford(s) << 32) | (unsigned)(4095 - col);
                bool pred = key > tau;
                unsigned mask = __ballot_sync(FULL, pred);
                if (pred) buf[cnt + __popc(mask & ((1u << lane) - 1u))] = key;
                cnt += __popc(mask);
                if (cnt >= 32) {
                    __syncwarp();
                    ull C = buf[lane];
                    int rem = cnt - 32;
                    if (lane < rem) buf[lane] = buf[32 + lane];
                    cnt = rem;
                    __syncwarp();
                    C = bsort32_desc(C, lane);
                    ull Crev = __shfl_sync(FULL, C, 31 - lane);
                    ull m = (L > Crev) ? L : Crev;
                    L = bmerge32_desc(m, lane);
                    tau = __shfl_sync(FULL, L, 29);
                    tau_s = unford((unsigned)(tau >> 32));
                }
            }
        }
        v = nv;
    }
    // final flush of leftovers (pad with 0-keys)
    {
        __syncwarp();
        ull C = (lane < cnt) ? buf[lane] : 0ull;
        C = bsort32_desc(C, lane);
        ull Crev = __shfl_sync(FULL, C, 31 - lane);
        ull m = (L > Crev) ? L : Crev;
        L = bmerge32_desc(m, lane);
    }

    // softmax over top-30 (L sorted desc; lane 0 = max)
    float val = unford((unsigned)(L >> 32));
    int idx = 4095 - (int)(L & 0xFFFFFFFFu);
    float vmax = __shfl_sync(FULL, val, 0);
    float e = (lane < TOPK) ? expf(val - vmax) : 0.f;
    float ssum = e;
#pragma unroll
    for (int o = 16; o; o >>= 1) ssum += __shfl_xor_sync(FULL, ssum, o);
    float p = e / ssum;

    // scatter the 30 probs (row already zeroed by score_kernel)
    if (lane < TOPK) attn[(size_t)row * N_TOK + idx] = p;

    // sparse ctx: ctx[n, h*64 + 2*lane .. +1] = sum_j p_j * V[idx_j]
    float2 acc = make_float2(0.f, 0.f);
    const float* vbase = g_v + h * 64 + 2 * lane;
#pragma unroll 6
    for (int j = 0; j < TOPK; ++j) {
        float pj = __shfl_sync(FULL, p, j);
        int ij = __shfl_sync(FULL, idx, j);
        float2 vv = *(const float2*)(vbase + (size_t)ij * 256);
        acc.x += pj * vv.x;
        acc.y += pj * vv.y;
    }
    *(float2*)(g_ctx + (size_t)n * 256 + h * 64 + 2 * lane) = acc;
}

// ---------------- K3: out-proj + residual -> g_resid ------------------------------
__global__ __launch_bounds__(256) void oproj_kernel(const float* __restrict__ Wo,
                                                    const float* __restrict__ bo,
                                                    const float* __restrict__ q_in) {
    gemm32_body<true>(g_ctx, Wo, bo, q_in, g_resid);
}

// ---------------- K4: row LayerNorm -> d_out[0 : N*D] -----------------------------
__global__ __launch_bounds__(256) void ln_kernel(const float* __restrict__ g,
                                                 const float* __restrict__ b,
                                                 float* __restrict__ out) {
    const int row = blockIdx.x;
    const int tid = threadIdx.x;
    float x = g_resid[(size_t)row * 256 + tid];
    float s = x, s2 = x * x;
#pragma unroll
    for (int o = 16; o; o >>= 1) {
        s += __shfl_xor_sync(0xFFFFFFFFu, s, o);
        s2 += __shfl_xor_sync(0xFFFFFFFFu, s2, o);
    }
    __shared__ float rs[8], rs2[8];
    const int w = tid >> 5, lane = tid & 31;
    if (lane == 0) { rs[w] = s; rs2[w] = s2; }
    __syncthreads();
    float tot = 0.f, tot2 = 0.f;
#pragma unroll
    for (int i = 0; i < 8; ++i) { tot += rs[i]; tot2 += rs2[i]; }
    float mu = tot * (1.0f / 256.0f);
    float var = tot2 * (1.0f / 256.0f) - mu * mu;
    float inv = rsqrtf(var + LN_EPS);
    out[(size_t)row * 256 + tid] = (x - mu) * inv * g[tid] + b[tid];
}

// ---------------- launch -----------------------------------------------------------
extern "C" void kernel_launch(void* const* d_in, const int* in_sizes, int n_in,
                              void* d_out, int out_size) {
    const float* key_in   = (const float*)d_in[0];
    const float* value_in = (const float*)d_in[1];
    const float* query_in = (const float*)d_in[2];
    const float* Wq = (const float*)d_in[3];
    const float* bq = (const float*)d_in[4];
    const float* Wk = (const float*)d_in[5];
    const float* bk = (const float*)d_in[6];
    const float* Wv = (const float*)d_in[7];
    const float* bv = (const float*)d_in[8];
    const float* Wo = (const float*)d_in[9];
    const float* bo = (const float*)d_in[10];
    const float* ln_g = (const float*)d_in[11];
    const float* ln_b = (const float*)d_in[12];

    float* out = (float*)d_out;
    float* attn = out + (size_t)N_TOK * DMODEL;

    // 1) Q/K/V projections (32x64 tiles, 1536 blocks)
    proj_kernel<<<dim3(4, 128, 3), 256>>>(query_in, key_in, value_in, Wq, bq, Wk,
                                          bk, Wv, bv);
    // 2a) dense scaled scores -> g_scores; attn zero-fill overlapped
    score_kernel<<<dim3(64, 32, 4), 256>>>(attn);
    // 2b) per-row top-30 (group-ballot fast path), softmax, scatter, sparse ctx
    topk_kernel<<<N_TOK * NHEAD / 8, 256>>>(attn);
    // 3) output projection + residual (32x64 tiles, 512 blocks)
    oproj_kernel<<<dim3(4, 128), 256>>>(Wo, bo, query_in);
    // 4) layernorm
    ln_kernel<<<N_TOK, 256>>>(ln_g, ln_b, out);
}

// round 8
// speedup vs baseline: 1.1565x; 1.1565x over previous
#include <cuda_runtime.h>
#include <math.h>
#include <math_constants.h>

#define N_TOK 4096
#define DMODEL 256
#define NHEAD 4
#define DHEAD 64
#define TOPK 30
#define SCALE 0.25f
#define LN_EPS 1e-5f

typedef unsigned long long ull;

// ---------------- scratch (static device allocations; no runtime alloc) ----------
__device__ float g_q[N_TOK * DMODEL];
__device__ float g_k[N_TOK * DMODEL];
__device__ float g_v[N_TOK * DMODEL];
__device__ float g_ctx[N_TOK * DMODEL];
__device__ float g_resid[N_TOK * DMODEL];
__device__ float g_scores[(size_t)NHEAD * N_TOK * N_TOK];  // 256 MB score scratch

// ---------------- packed fp32x2 helpers ------------------------------------------
__device__ __forceinline__ void fma2(ull& d, ull a, ull b) {
    asm("fma.rn.f32x2 %0, %1, %2, %0;" : "+l"(d) : "l"(a), "l"(b));
}
__device__ __forceinline__ float2 unpack2(ull v) {
    float2 f;
    asm("mov.b64 {%0, %1}, %2;" : "=f"(f.x), "=f"(f.y) : "l"(v));
    return f;
}
// monotone float->uint map (ascending)
__device__ __forceinline__ unsigned ford(float f) {
    unsigned u = __float_as_uint(f);
    return (u & 0x80000000u) ? ~u : (u | 0x80000000u);
}
__device__ __forceinline__ float unford(unsigned u) {
    return __uint_as_float((u & 0x80000000u) ? (u & 0x7FFFFFFFu) : ~u);
}

// ---- warp bitonic: sort 32 ull (1/lane) DESCENDING across lanes -------------------
__device__ __forceinline__ ull bsort32_desc(ull k, int lane) {
#pragma unroll
    for (int size = 2; size <= 32; size <<= 1) {
#pragma unroll
        for (int stride = size >> 1; stride >= 1; stride >>= 1) {
            ull o = __shfl_xor_sync(0xFFFFFFFFu, k, stride);
            bool desc = ((lane & size) == 0);
            bool lower = ((lane & stride) == 0);
            bool takemax = (lower == desc);
            ull mx = (k > o) ? k : o;
            ull mn = (k > o) ? o : k;
            k = takemax ? mx : mn;
        }
    }
    return k;
}
// bitonic merge (input bitonic) -> descending
__device__ __forceinline__ ull bmerge32_desc(ull k, int lane) {
#pragma unroll
    for (int stride = 16; stride >= 1; stride >>= 1) {
        ull o = __shfl_xor_sync(0xFFFFFFFFu, k, stride);
        bool lower = ((lane & stride) == 0);
        ull mx = (k > o) ? k : o;
        ull mn = (k > o) ? o : k;
        k = lower ? mx : mn;
    }
    return k;
}

// ---------------- 64x64-tile fp32 GEMM body: C = A @ B^T (+bias)(+res) -----------
template <bool ADD_RES>
__device__ __forceinline__ void gemm64_body(const float* __restrict__ A,
                                            const float* __restrict__ B,
                                            const float* __restrict__ bias,
                                            const float* __restrict__ res,
                                            float* __restrict__ C) {
    __shared__ ull As[64 * 33];
    __shared__ ull Bs[64 * 33];
    const int tid = threadIdx.x;
    const int bm = blockIdx.y * 64;
    const int bn = blockIdx.x * 64;
    const int qg = (tid & 7) | ((tid >> 7) << 3);
    const int kg = (tid >> 3) & 15;

    ull acc[4][4];
#pragma unroll
    for (int a = 0; a < 4; ++a)
#pragma unroll
        for (int b = 0; b < 4; ++b) acc[a][b] = 0ull;

    for (int kk = 0; kk < 256; kk += 64) {
        __syncthreads();
#pragma unroll
        for (int i = 0; i < 8; ++i) {
            int idx = tid + i * 256;
            int r = idx >> 5, c = idx & 31;
            As[r * 33 + c] = *(const ull*)(A + (size_t)(bm + r) * 256 + kk + c * 2);
            Bs[r * 33 + c] = *(const ull*)(B + (size_t)(bn + r) * 256 + kk + c * 2);
        }
        __syncthreads();
#pragma unroll 8
        for (int d2 = 0; d2 < 32; ++d2) {
            ull qv[4], kv[4];
#pragma unroll
            for (int a = 0; a < 4; ++a) qv[a] = As[(qg * 4 + a) * 33 + d2];
#pragma unroll
            for (int b = 0; b < 4; ++b) kv[b] = Bs[(kg * 4 + b) * 33 + d2];
#pragma unroll
            for (int a = 0; a < 4; ++a)
#pragma unroll
                for (int b = 0; b < 4; ++b) fma2(acc[a][b], qv[a], kv[b]);
        }
    }
#pragma unroll
    for (int a = 0; a < 4; ++a) {
        int row = bm + qg * 4 + a;
#pragma unroll
        for (int b = 0; b < 4; ++b) {
            int col = bn + kg * 4 + b;
            float2 f = unpack2(acc[a][b]);
            float v = f.x + f.y + bias[col];
            if (ADD_RES) v += res[(size_t)row * 256 + col];
            C[(size_t)row * 256 + col] = v;
        }
    }
}

// ---------------- K1: fused Q/K/V projections -------------------------------------
__global__ __launch_bounds__(256) void proj_kernel(
    const float* __restrict__ q_in, const float* __restrict__ k_in,
    const float* __restrict__ v_in, const float* __restrict__ Wq,
    const float* __restrict__ bq, const float* __restrict__ Wk,
    const float* __restrict__ bk, const float* __restrict__ Wv,
    const float* __restrict__ bv) {
    const float *A, *B, *bias;
    float* C;
    if (blockIdx.z == 0) { A = q_in; B = Wq; bias = bq; C = g_q; }
    else if (blockIdx.z == 1) { A = k_in; B = Wk; bias = bk; C = g_k; }
    else { A = v_in; B = Wv; bias = bv; C = g_v; }
    gemm64_body<false>(A, B, bias, nullptr, C);
}

// ---------------- K2a: dense score GEMM -> g_scores; zero attn tile ----------------
// grid: (64 kb, 32 qb, 4 h). block 256. tile 128(q) x 64(k). micro 8x4 in ull.
__global__ __launch_bounds__(256, 2) void score_kernel(float* __restrict__ attn) {
    __shared__ ull Qs[128 * 32];
    __shared__ ull Ks[64 * 32];
    const int tid = threadIdx.x;
    const int h = blockIdx.z;
    const int qb0 = blockIdx.y * 128;
    const int kb0 = blockIdx.x * 64;
    const int kg = tid & 15;   // 16 col-groups of 4
    const int qg = tid >> 4;   // 16 row-groups of 8

    // zero-fill this block's attn tile (rows qb0..+128, cols kb0..+64), streaming
    {
        const float4 z4 = make_float4(0.f, 0.f, 0.f, 0.f);
#pragma unroll
        for (int i = 0; i < 8; ++i) {
            int idx = tid + i * 256;
            int r = idx >> 4, c4 = idx & 15;
            __stcs((float4*)(attn + (size_t)(h * N_TOK + qb0 + r) * N_TOK + kb0 +
                             c4 * 4),
                   z4);
        }
    }

    // fill Q tile: 4096 ull, swizzle c ^ (r>>3)
#pragma unroll
    for (int i = 0; i < 16; ++i) {
        int idx = tid + i * 256;
        int r = idx >> 5, c = idx & 31;
        Qs[(r << 5) | (c ^ (r >> 3))] =
            *(const ull*)(g_q + (size_t)(qb0 + r) * 256 + h * 64 + c * 2);
    }
    // fill K tile: 2048 ull, swizzle c ^ (r>>2)
#pragma unroll
    for (int i = 0; i < 8; ++i) {
        int idx = tid + i * 256;
        int r = idx >> 5, c = idx & 31;
        Ks[(r << 5) | (c ^ (r >> 2))] =
            *(const ull*)(g_k + (size_t)(kb0 + r) * 256 + h * 64 + c * 2);
    }
    __syncthreads();

    ull acc[8][4];
#pragma unroll
    for (int a = 0; a < 8; ++a)
#pragma unroll
        for (int b = 0; b < 4; ++b) acc[a][b] = 0ull;

#pragma unroll 4
    for (int d2 = 0; d2 < 32; ++d2) {
        ull qv[8], kv[4];
#pragma unroll
        for (int a = 0; a < 8; ++a) qv[a] = Qs[((qg * 8 + a) << 5) | (d2 ^ qg)];
#pragma unroll
        for (int b = 0; b < 4; ++b) kv[b] = Ks[((kg * 4 + b) << 5) | (d2 ^ kg)];
#pragma unroll
        for (int a = 0; a < 8; ++a)
#pragma unroll
            for (int b = 0; b < 4; ++b) fma2(acc[a][b], qv[a], kv[b]);
    }

#pragma unroll
    for (int a = 0; a < 8; ++a) {
        int row = qb0 + qg * 8 + a;
        float4 o;
        float2 f0 = unpack2(acc[a][0]);
        float2 f1 = unpack2(acc[a][1]);
        float2 f2 = unpack2(acc[a][2]);
        float2 f3 = unpack2(acc[a][3]);
        o.x = (f0.x + f0.y) * SCALE;
        o.y = (f1.x + f1.y) * SCALE;
        o.z = (f2.x + f2.y) * SCALE;
        o.w = (f3.x + f3.y) * SCALE;
        __stcs((float4*)(g_scores + ((size_t)(h * N_TOK + row)) * N_TOK + kb0 +
                         kg * 4),
               o);
    }
}

// ---------------- K2b: warp-per-row top-30, group-ballot fast path, MLP=2 ---------
__global__ __launch_bounds__(256) void topk_kernel(float* __restrict__ attn) {
    __shared__ ull bufs[8][64];
    const unsigned FULL = 0xFFFFFFFFu;
    const int warp = threadIdx.x >> 5, lane = threadIdx.x & 31;
    const int row = blockIdx.x * 8 + warp;  // = h*4096 + n
    const int h = row >> 12;
    const int n = row & 4095;
    const float4* p4 = (const float4*)(g_scores + (size_t)row * N_TOK);
    ull* buf = bufs[warp];

    ull L = 0ull;                    // sorted desc top-32 (1/lane)
    ull tau = 0ull;                  // 30th-best 64-bit key so far
    float tau_s = -CUDART_INF_F;     // fp32 score of tau (fast-path filter)
    int cnt = 0;                     // pending candidates in buf

    float4 v0 = __ldcs(p4 + lane);
    float4 v1 = __ldcs(p4 + 32 + lane);
    for (int c = 0; c < 32; ++c) {
        float4 v = v0;
        v0 = v1;
        if (c + 2 < 32) v1 = __ldcs(p4 + (c + 2) * 32 + lane);  // 2-deep prefetch
        float m4 = fmaxf(fmaxf(v.x, v.y), fmaxf(v.z, v.w));
        // fast path: one ballot per 4 elements. s > tau_s => key > tau (ford
        // monotone); equals fall into the exact 64-bit slow path.
        if (__ballot_sync(FULL, m4 >= tau_s) != 0) {
#pragma unroll
            for (int j = 0; j < 4; ++j) {
                float s = (j == 0) ? v.x : (j == 1) ? v.y : (j == 2) ? v.z : v.w;
                int col = c * 128 + lane * 4 + j;
                ull key = ((ull)ford(s) << 32) | (unsigned)(4095 - col);
                bool pred = key > tau;
                unsigned mask = __ballot_sync(FULL, pred);
                if (pred) buf[cnt + __popc(mask & ((1u << lane) - 1u))] = key;
                cnt += __popc(mask);
                if (cnt >= 32) {
                    __syncwarp();
                    ull C = buf[lane];
                    int rem = cnt - 32;
                    if (lane < rem) buf[lane] = buf[32 + lane];
                    cnt = rem;
                    __syncwarp();
                    C = bsort32_desc(C, lane);
                    ull Crev = __shfl_sync(FULL, C, 31 - lane);
                    ull m = (L > Crev) ? L : Crev;
                    L = bmerge32_desc(m, lane);
                    tau = __shfl_sync(FULL, L, 29);
                    tau_s = unford((unsigned)(tau >> 32));
                }
            }
        }
    }
    // final flush of leftovers (pad with 0-keys)
    {
        __syncwarp();
        ull C = (lane < cnt) ? buf[lane] : 0ull;
        C = bsort32_desc(C, lane);
        ull Crev = __shfl_sync(FULL, C, 31 - lane);
        ull m = (L > Crev) ? L : Crev;
        L = bmerge32_desc(m, lane);
    }

    // softmax over top-30 (L sorted desc; lane 0 = max)
    float val = unford((unsigned)(L >> 32));
    int idx = 4095 - (int)(L & 0xFFFFFFFFu);
    float vmax = __shfl_sync(FULL, val, 0);
    float e = (lane < TOPK) ? expf(val - vmax) : 0.f;
    float ssum = e;
#pragma unroll
    for (int o = 16; o; o >>= 1) ssum += __shfl_xor_sync(FULL, ssum, o);
    float p = e / ssum;

    // scatter the 30 probs (row already zeroed by score_kernel)
    if (lane < TOPK) attn[(size_t)row * N_TOK + idx] = p;

    // sparse ctx: ctx[n, h*64 + 2*lane .. +1] = sum_j p_j * V[idx_j]
    float2 acc = make_float2(0.f, 0.f);
    const float* vbase = g_v + h * 64 + 2 * lane;
#pragma unroll 6
    for (int j = 0; j < TOPK; ++j) {
        float pj = __shfl_sync(FULL, p, j);
        int ij = __shfl_sync(FULL, idx, j);
        float2 vv = *(const float2*)(vbase + (size_t)ij * 256);
        acc.x += pj * vv.x;
        acc.y += pj * vv.y;
    }
    *(float2*)(g_ctx + (size_t)n * 256 + h * 64 + 2 * lane) = acc;
}

// ---------------- K3: out-proj + residual -> g_resid ------------------------------
__global__ __launch_bounds__(256) void oproj_kernel(const float* __restrict__ Wo,
                                                    const float* __restrict__ bo,
                                                    const float* __restrict__ q_in) {
    gemm64_body<true>(g_ctx, Wo, bo, q_in, g_resid);
}

// ---------------- K4: row LayerNorm -> d_out[0 : N*D] -----------------------------
__global__ __launch_bounds__(256) void ln_kernel(const float* __restrict__ g,
                                                 const float* __restrict__ b,
                                                 float* __restrict__ out) {
    const int row = blockIdx.x;
    const int tid = threadIdx.x;
    float x = g_resid[(size_t)row * 256 + tid];
    float s = x, s2 = x * x;
#pragma unroll
    for (int o = 16; o; o >>= 1) {
        s += __shfl_xor_sync(0xFFFFFFFFu, s, o);
        s2 += __shfl_xor_sync(0xFFFFFFFFu, s2, o);
    }
    __shared__ float rs[8], rs2[8];
    const int w = tid >> 5, lane = tid & 31;
    if (lane == 0) { rs[w] = s; rs2[w] = s2; }
    __syncthreads();
    float tot = 0.f, tot2 = 0.f;
#pragma unroll
    for (int i = 0; i < 8; ++i) { tot += rs[i]; tot2 += rs2[i]; }
    float mu = tot * (1.0f / 256.0f);
    float var = tot2 * (1.0f / 256.0f) - mu * mu;
    float inv = rsqrtf(var + LN_EPS);
    out[(size_t)row * 256 + tid] = (x - mu) * inv * g[tid] + b[tid];
}

// ---------------- launch -----------------------------------------------------------
extern "C" void kernel_launch(void* const* d_in, const int* in_sizes, int n_in,
                              void* d_out, int out_size) {
    const float* key_in   = (const float*)d_in[0];
    const float* value_in = (const float*)d_in[1];
    const float* query_in = (const float*)d_in[2];
    const float* Wq = (const float*)d_in[3];
    const float* bq = (const float*)d_in[4];
    const float* Wk = (const float*)d_in[5];
    const float* bk = (const float*)d_in[6];
    const float* Wv = (const float*)d_in[7];
    const float* bv = (const float*)d_in[8];
    const float* Wo = (const float*)d_in[9];
    const float* bo = (const float*)d_in[10];
    const float* ln_g = (const float*)d_in[11];
    const float* ln_b = (const float*)d_in[12];

    float* out = (float*)d_out;
    float* attn = out + (size_t)N_TOK * DMODEL;

    // 1) Q/K/V projections (64x64 tiles, 768 blocks)
    proj_kernel<<<dim3(4, 64, 3), 256>>>(query_in, key_in, value_in, Wq, bq, Wk, bk,
                                         Wv, bv);
    // 2a) dense scaled scores -> g_scores; attn zero-fill overlapped
    score_kernel<<<dim3(64, 32, 4), 256>>>(attn);
    // 2b) per-row top-30 (group-ballot fast path, 2-deep prefetch)
    topk_kernel<<<N_TOK * NHEAD / 8, 256>>>(attn);
    // 3) output projection + residual (64x64 tiles, 256 blocks)
    oproj_kernel<<<dim3(4, 64), 256>>>(Wo, bo, query_in);
    // 4) layernorm
    ln_kernel<<<N_TOK, 256>>>(ln_g, ln_b, out);
}